// round 2
// baseline (speedup 1.0000x reference)
#include <cuda_runtime.h>
#include <cstdint>

// Problem dims (fixed by the dataset)
#define M_TOT 16384   // B*L
#define N_TOT 2048    // 2*D
#define K_TOT 1024    // D
#define BATCH 4
#define SEQL  4096
#define DIM   1024
#define NCHUNK 32
#define CHUNK  128    // SEQL / NCHUNK

// ---------------- scratch (static device allocations only) ----------------
__device__ float g_hg[(size_t)M_TOT * N_TOT];            // 134 MB: GEMM output
__device__ float g_sumP[BATCH * NCHUNK * DIM];           // per-chunk coeff product
__device__ float g_sumH[BATCH * NCHUNK * DIM];           // per-chunk local scan end
__device__ float g_hstart[BATCH * NCHUNK * DIM];         // per-chunk carry-in

// ---------------- packed f32x2 helpers (sm_100+) ----------------
__device__ __forceinline__ unsigned long long pack2(float lo, float hi) {
    unsigned long long r;
    asm("mov.b64 %0, {%1, %2};" : "=l"(r) : "f"(lo), "f"(hi));
    return r;
}
__device__ __forceinline__ void unpack2(unsigned long long v, float& lo, float& hi) {
    asm("mov.b64 {%0, %1}, %2;" : "=f"(lo), "=f"(hi) : "l"(v));
}
__device__ __forceinline__ unsigned long long fma2(unsigned long long a,
                                                   unsigned long long b,
                                                   unsigned long long c) {
    unsigned long long d;
    asm("fma.rn.f32x2 %0, %1, %2, %3;" : "=l"(d) : "l"(a), "l"(b), "l"(c));
    return d;
}

// ---------------- GEMM: hg[m,e] = sum_k X[m,k] * W[e,k] ----------------
#define BM 128
#define BN 128
#define BK 16
#define PADM 132   // BM + 4 floats pad; rows stay 16B aligned (132*4 = 33*16)
#define PADN 132

__global__ __launch_bounds__(256, 2)
void gemm_kernel(const float* __restrict__ A, const float* __restrict__ Bw) {
    __shared__ float As[2][BK][PADM];
    __shared__ float Bs[2][BK][PADN];

    const int tid = threadIdx.x;
    const int bm = blockIdx.y * BM;
    const int bn = blockIdx.x * BN;
    const int r = tid >> 4;   // 0..15 -> m micro-tile row group
    const int c = tid & 15;   // 0..15 -> n micro-tile col group

    // tile-load mapping: 512 float4 per operand tile, 2 per thread
    const int ar0 = tid >> 2;          // 0..63
    const int ak0 = (tid & 3) * 4;     // 0,4,8,12

    unsigned long long acc[4][8];
#pragma unroll
    for (int i = 0; i < 4; i++)
#pragma unroll
        for (int j = 0; j < 8; j++) acc[i][j] = 0ull;

    float4 ra0, ra1, rb0, rb1;

    // prologue: load k-tile 0
    {
        const float* Ap = A + (size_t)(bm + ar0) * K_TOT + ak0;
        const float* Bp = Bw + (size_t)(bn + ar0) * K_TOT + ak0;
        ra0 = *(const float4*)(Ap);
        ra1 = *(const float4*)(Ap + (size_t)64 * K_TOT);
        rb0 = *(const float4*)(Bp);
        rb1 = *(const float4*)(Bp + (size_t)64 * K_TOT);
    }
    {
        As[0][ak0 + 0][ar0] = ra0.x; As[0][ak0 + 1][ar0] = ra0.y;
        As[0][ak0 + 2][ar0] = ra0.z; As[0][ak0 + 3][ar0] = ra0.w;
        As[0][ak0 + 0][ar0 + 64] = ra1.x; As[0][ak0 + 1][ar0 + 64] = ra1.y;
        As[0][ak0 + 2][ar0 + 64] = ra1.z; As[0][ak0 + 3][ar0 + 64] = ra1.w;
        Bs[0][ak0 + 0][ar0] = rb0.x; Bs[0][ak0 + 1][ar0] = rb0.y;
        Bs[0][ak0 + 2][ar0] = rb0.z; Bs[0][ak0 + 3][ar0] = rb0.w;
        Bs[0][ak0 + 0][ar0 + 64] = rb1.x; Bs[0][ak0 + 1][ar0 + 64] = rb1.y;
        Bs[0][ak0 + 2][ar0 + 64] = rb1.z; Bs[0][ak0 + 3][ar0 + 64] = rb1.w;
    }
    __syncthreads();

    const int NT = K_TOT / BK;   // 64
#pragma unroll 1
    for (int t = 0; t < NT; t++) {
        const int cur = t & 1;
        if (t + 1 < NT) {
            const int kt = (t + 1) * BK;
            const float* Ap = A + (size_t)(bm + ar0) * K_TOT + kt + ak0;
            const float* Bp = Bw + (size_t)(bn + ar0) * K_TOT + kt + ak0;
            ra0 = *(const float4*)(Ap);
            ra1 = *(const float4*)(Ap + (size_t)64 * K_TOT);
            rb0 = *(const float4*)(Bp);
            rb1 = *(const float4*)(Bp + (size_t)64 * K_TOT);
        }

#pragma unroll
        for (int k = 0; k < BK; k++) {
            float4 a0 = *(const float4*)&As[cur][k][r * 8];
            float4 a1 = *(const float4*)&As[cur][k][r * 8 + 4];
            float4 b0 = *(const float4*)&Bs[cur][k][c * 8];
            float4 b1 = *(const float4*)&Bs[cur][k][c * 8 + 4];
            unsigned long long ap[4];
            ap[0] = pack2(a0.x, a0.y); ap[1] = pack2(a0.z, a0.w);
            ap[2] = pack2(a1.x, a1.y); ap[3] = pack2(a1.z, a1.w);
            unsigned long long bd[8];
            bd[0] = pack2(b0.x, b0.x); bd[1] = pack2(b0.y, b0.y);
            bd[2] = pack2(b0.z, b0.z); bd[3] = pack2(b0.w, b0.w);
            bd[4] = pack2(b1.x, b1.x); bd[5] = pack2(b1.y, b1.y);
            bd[6] = pack2(b1.z, b1.z); bd[7] = pack2(b1.w, b1.w);
#pragma unroll
            for (int i = 0; i < 4; i++)
#pragma unroll
                for (int j = 0; j < 8; j++)
                    acc[i][j] = fma2(ap[i], bd[j], acc[i][j]);
        }

        if (t + 1 < NT) {
            const int nxt = cur ^ 1;
            As[nxt][ak0 + 0][ar0] = ra0.x; As[nxt][ak0 + 1][ar0] = ra0.y;
            As[nxt][ak0 + 2][ar0] = ra0.z; As[nxt][ak0 + 3][ar0] = ra0.w;
            As[nxt][ak0 + 0][ar0 + 64] = ra1.x; As[nxt][ak0 + 1][ar0 + 64] = ra1.y;
            As[nxt][ak0 + 2][ar0 + 64] = ra1.z; As[nxt][ak0 + 3][ar0 + 64] = ra1.w;
            Bs[nxt][ak0 + 0][ar0] = rb0.x; Bs[nxt][ak0 + 1][ar0] = rb0.y;
            Bs[nxt][ak0 + 2][ar0] = rb0.z; Bs[nxt][ak0 + 3][ar0] = rb0.w;
            Bs[nxt][ak0 + 0][ar0 + 64] = rb1.x; Bs[nxt][ak0 + 1][ar0 + 64] = rb1.y;
            Bs[nxt][ak0 + 2][ar0 + 64] = rb1.z; Bs[nxt][ak0 + 3][ar0 + 64] = rb1.w;
        }
        __syncthreads();
    }

    // epilogue: unpack and store
#pragma unroll
    for (int i = 0; i < 4; i++) {
        float lo[8], hi[8];
#pragma unroll
        for (int j = 0; j < 8; j++) unpack2(acc[i][j], lo[j], hi[j]);
        const size_t m0 = (size_t)(bm + r * 8 + 2 * i);
        float* p0 = g_hg + m0 * N_TOT + bn + c * 8;
        ((float4*)p0)[0] = make_float4(lo[0], lo[1], lo[2], lo[3]);
        ((float4*)p0)[1] = make_float4(lo[4], lo[5], lo[6], lo[7]);
        float* p1 = p0 + N_TOT;
        ((float4*)p1)[0] = make_float4(hi[0], hi[1], hi[2], hi[3]);
        ((float4*)p1)[1] = make_float4(hi[4], hi[5], hi[6], hi[7]);
    }
}

// ---------------- scan: h_l = c_l*h_{l-1} + z_l*g_l ----------------
// z = sigmoid(gate), c = sigmoid(-gate), g = hid>=0 ? hid+0.5 : sigmoid(hid)
__device__ __forceinline__ void scan_terms(float hid, float gat, float& cc,
                                           float& zg) {
    float e = __expf(-gat);
    float z = __fdividef(1.f, 1.f + e);
    cc = e * z;                               // sigmoid(-gate)
    float eh = __expf(-fabsf(hid));
    float sg = __fdividef(eh, 1.f + eh);      // sigmoid(hid) when hid<0
    float g = (hid >= 0.f) ? (hid + 0.5f) : sg;
    zg = z * g;
}

// Phase 1: per (b, chunk, 32-channel group): local scan from h=0, record
// (prod c, local end value)
__global__ void scan_phase1() {
    const int gw = (blockIdx.x * blockDim.x + threadIdx.x) >> 5;   // 0..4095
    const int lane = threadIdx.x & 31;
    const int chunk = gw & (NCHUNK - 1);
    const int dg = (gw >> 5) & 31;
    const int b = gw >> 10;
    const int d = dg * 32 + lane;

    const float* __restrict__ hg = g_hg;
    size_t base = ((size_t)(b * SEQL + chunk * CHUNK)) * N_TOT + d;
    float h = 0.f, p = 1.f;
#pragma unroll 8
    for (int l = 0; l < CHUNK; l++) {
        float hid = __ldg(hg + base + (size_t)l * N_TOT);
        float gat = __ldg(hg + base + (size_t)l * N_TOT + DIM);
        float cc, zg;
        scan_terms(hid, gat, cc, zg);
        h = cc * h + zg;
        p *= cc;
    }
    const int sidx = (b * NCHUNK + chunk) * DIM + d;
    g_sumH[sidx] = h;
    g_sumP[sidx] = p;
}

// Phase 2: sequential combine across chunks (per (b,d) channel)
__global__ void scan_phase2() {
    const int idx = blockIdx.x * blockDim.x + threadIdx.x;   // 0..4095
    const int b = idx >> 10;
    const int d = idx & (DIM - 1);
    float carry = 0.f;
#pragma unroll
    for (int ch = 0; ch < NCHUNK; ch++) {
        const int s = (b * NCHUNK + ch) * DIM + d;
        g_hstart[s] = carry;
        carry = g_sumP[s] * carry + g_sumH[s];
    }
}

// Phase 3: replay with correct carry-in, write output
__global__ void scan_phase3(float* __restrict__ out) {
    const int gw = (blockIdx.x * blockDim.x + threadIdx.x) >> 5;
    const int lane = threadIdx.x & 31;
    const int chunk = gw & (NCHUNK - 1);
    const int dg = (gw >> 5) & 31;
    const int b = gw >> 10;
    const int d = dg * 32 + lane;

    const float* __restrict__ hg = g_hg;
    size_t base = ((size_t)(b * SEQL + chunk * CHUNK)) * N_TOT + d;
    size_t obase = ((size_t)(b * SEQL + chunk * CHUNK)) * DIM + d;
    float h = g_hstart[(b * NCHUNK + chunk) * DIM + d];
#pragma unroll 8
    for (int l = 0; l < CHUNK; l++) {
        float hid = __ldg(hg + base + (size_t)l * N_TOT);
        float gat = __ldg(hg + base + (size_t)l * N_TOT + DIM);
        float cc, zg;
        scan_terms(hid, gat, cc, zg);
        h = cc * h + zg;
        out[obase + (size_t)l * DIM] = h;
    }
}

// ---------------- launch ----------------
extern "C" void kernel_launch(void* const* d_in, const int* in_sizes, int n_in,
                              void* d_out, int out_size) {
    const float* x = (const float*)d_in[0];   // [4,4096,1024]
    const float* W = (const float*)d_in[1];   // [2048,1024]
    float* out = (float*)d_out;               // [4,4096,1024]

    dim3 ggrid(N_TOT / BN, M_TOT / BM);       // (16, 128)
    gemm_kernel<<<ggrid, 256>>>(x, W);

    // 4096 warps of scan work = 131072 threads
    scan_phase1<<<512, 256>>>();
    scan_phase2<<<16, 256>>>();
    scan_phase3<<<512, 256>>>(out);
}

// round 4
// speedup vs baseline: 2.5026x; 2.5026x over previous
#include <cuda_runtime.h>
#include <cuda_fp16.h>
#include <cstdint>

// Problem dims (fixed)
#define M_TOT 16384   // B*L
#define N_TOT 2048    // 2*D
#define K_TOT 1024    // D
#define BATCH 4
#define SEQL  4096
#define DIM   1024
#define NCHUNK 32
#define CHUNK  128

// ---------------- scratch ----------------
__device__ __align__(256) float  g_hg[(size_t)M_TOT * N_TOT];     // 134MB GEMM out
__device__ __align__(256) __half g_xhi[(size_t)M_TOT * K_TOT];
__device__ __align__(256) __half g_xlo[(size_t)M_TOT * K_TOT];
__device__ __align__(256) __half g_whi[(size_t)N_TOT * K_TOT];
__device__ __align__(256) __half g_wlo[(size_t)N_TOT * K_TOT];
__device__ float g_sumP[BATCH * NCHUNK * DIM];
__device__ float g_sumH[BATCH * NCHUNK * DIM];
__device__ float g_hstart[BATCH * NCHUNK * DIM];

// ---------------- PTX helpers (base sm_100 legal only) ----------------
__device__ __forceinline__ uint32_t smem_u32(const void* p) {
    uint32_t a;
    asm("{ .reg .u64 t; cvta.to.shared.u64 t, %1; cvt.u32.u64 %0, t; }"
        : "=r"(a) : "l"(p));
    return a;
}
__device__ __forceinline__ void cp16(uint32_t dst, const void* src) {
    asm volatile("cp.async.cg.shared.global [%0], [%1], 16;" :: "r"(dst), "l"(src));
}
#define CP_COMMIT() asm volatile("cp.async.commit_group;" ::: "memory")
#define CP_WAIT0()  asm volatile("cp.async.wait_group 0;" ::: "memory")
#define CP_WAIT1()  asm volatile("cp.async.wait_group 1;" ::: "memory")

#define LDSM4(r0, r1, r2, r3, a) \
    asm volatile("ldmatrix.sync.aligned.m8n8.x4.shared.b16 {%0,%1,%2,%3}, [%4];" \
                 : "=r"(r0), "=r"(r1), "=r"(r2), "=r"(r3) : "r"(a))
#define LDSM2(r0, r1, a) \
    asm volatile("ldmatrix.sync.aligned.m8n8.x2.shared.b16 {%0,%1}, [%2];" \
                 : "=r"(r0), "=r"(r1) : "r"(a))

#define MMA16816(c, a, b) \
    asm volatile( \
        "mma.sync.aligned.m16n8k16.row.col.f32.f16.f16.f32 " \
        "{%0,%1,%2,%3}, {%4,%5,%6,%7}, {%8,%9}, {%0,%1,%2,%3};" \
        : "+f"((c)[0]), "+f"((c)[1]), "+f"((c)[2]), "+f"((c)[3]) \
        : "r"((a)[0]), "r"((a)[1]), "r"((a)[2]), "r"((a)[3]), \
          "r"((b)[0]), "r"((b)[1]))

// ---------------- fp16 split kernel ----------------
__global__ void split_kernel(const float* __restrict__ src,
                             __half* __restrict__ hi, __half* __restrict__ lo,
                             int n4) {
    int i = blockIdx.x * blockDim.x + threadIdx.x;
    if (i >= n4) return;
    float4 v = reinterpret_cast<const float4*>(src)[i];
    __half h0 = __float2half_rn(v.x), h1 = __float2half_rn(v.y);
    __half h2 = __float2half_rn(v.z), h3 = __float2half_rn(v.w);
    __half l0 = __float2half_rn(v.x - __half2float(h0));
    __half l1 = __float2half_rn(v.y - __half2float(h1));
    __half l2 = __float2half_rn(v.z - __half2float(h2));
    __half l3 = __float2half_rn(v.w - __half2float(h3));
    reinterpret_cast<__half2*>(hi)[2 * i]     = __halves2half2(h0, h1);
    reinterpret_cast<__half2*>(hi)[2 * i + 1] = __halves2half2(h2, h3);
    reinterpret_cast<__half2*>(lo)[2 * i]     = __halves2half2(l0, l1);
    reinterpret_cast<__half2*>(lo)[2 * i + 1] = __halves2half2(l2, l3);
}

// ---------------- mma.sync GEMM: 128M x 128N per CTA, BK=64 ----------------
// Smem row = 64 halves = 128B; 16B chunks swizzled: chunk ^= (row & 7)
#define OFF_AHI 0
#define OFF_ALO 16384
#define OFF_BHI 32768
#define OFF_BLO 49152
#define STAGE_BYTES 65536
#define SMEM_DYN (2 * STAGE_BYTES)
#define NT (K_TOT / 64)   // 16

__device__ __forceinline__ void load_stage(uint32_t sbase, int buf, int kc,
                                           int bm, int bn, int tid) {
    uint32_t s = sbase + (uint32_t)buf * STAGE_BYTES;
#pragma unroll
    for (int i = 0; i < 4; i++) {
        int ch = tid + i * 256;           // 0..1023
        int row = ch >> 3, c = ch & 7;
        uint32_t off = (uint32_t)(row * 128) + (uint32_t)((c ^ (row & 7)) << 4);
        const __half* ah = g_xhi + (size_t)(bm + row) * K_TOT + kc + c * 8;
        const __half* al = g_xlo + (size_t)(bm + row) * K_TOT + kc + c * 8;
        cp16(s + OFF_AHI + off, ah);
        cp16(s + OFF_ALO + off, al);
        const __half* bh = g_whi + (size_t)(bn + row) * K_TOT + kc + c * 8;
        const __half* bl = g_wlo + (size_t)(bn + row) * K_TOT + kc + c * 8;
        cp16(s + OFF_BHI + off, bh);
        cp16(s + OFF_BLO + off, bl);
    }
    CP_COMMIT();
}

__global__ __launch_bounds__(256, 1) void gemm_mma_kernel() {
    extern __shared__ __align__(1024) char dyn_smem[];
    const int tid = threadIdx.x;
    const int wid = tid >> 5;
    const int lane = tid & 31;
    const int bm = blockIdx.y * 128;
    const int bn = blockIdx.x * 128;
    const int warp_m = wid & 1;     // 2 warps along M (64 rows each)
    const int warp_n = wid >> 1;    // 4 warps along N (32 cols each)

    uint32_t sbase = smem_u32(dyn_smem);

    // per-lane ldmatrix row precompute
    const int j4 = lane >> 3;            // matrix index for x4
    const int rin = lane & 7;
    const int a_moff = (j4 & 1) * 8 + rin;
    const int a_kj = j4 >> 1;            // 0/1: k-chunk within k16
    int aoff[4], asw[4];
#pragma unroll
    for (int i = 0; i < 4; i++) {
        int r = warp_m * 64 + i * 16 + a_moff;
        aoff[i] = r * 128;
        asw[i] = r & 7;
    }
    const int b_kj = (lane >> 3) & 1;    // matrix index for x2
    int boff[4], bsw[4];
#pragma unroll
    for (int j = 0; j < 4; j++) {
        int r = warp_n * 32 + j * 8 + rin;
        boff[j] = r * 128;
        bsw[j] = r & 7;
    }

    float acc[4][4][4];
#pragma unroll
    for (int i = 0; i < 4; i++)
#pragma unroll
        for (int j = 0; j < 4; j++)
#pragma unroll
            for (int q = 0; q < 4; q++) acc[i][j][q] = 0.f;

    load_stage(sbase, 0, 0, bm, bn, tid);

#pragma unroll 1
    for (int t = 0; t < NT; t++) {
        const int cur = t & 1;
        if (t + 1 < NT) {
            load_stage(sbase, cur ^ 1, (t + 1) * 64, bm, bn, tid);
            CP_WAIT1();
        } else {
            CP_WAIT0();
        }
        __syncthreads();

        const uint32_t s = sbase + (uint32_t)cur * STAGE_BYTES;
        const uint32_t sAhi = s + OFF_AHI, sAlo = s + OFF_ALO;
        const uint32_t sBhi = s + OFF_BHI, sBlo = s + OFF_BLO;

#pragma unroll
        for (int ks = 0; ks < 4; ks++) {
            uint32_t Ahi[4][4], Alo[4][4], Bhi[4][2], Blo[4][2];
#pragma unroll
            for (int i = 0; i < 4; i++) {
                uint32_t co = (uint32_t)(((ks * 2 + a_kj) ^ asw[i]) << 4);
                LDSM4(Ahi[i][0], Ahi[i][1], Ahi[i][2], Ahi[i][3],
                      sAhi + aoff[i] + co);
                LDSM4(Alo[i][0], Alo[i][1], Alo[i][2], Alo[i][3],
                      sAlo + aoff[i] + co);
            }
#pragma unroll
            for (int j = 0; j < 4; j++) {
                uint32_t co = (uint32_t)(((ks * 2 + b_kj) ^ bsw[j]) << 4);
                LDSM2(Bhi[j][0], Bhi[j][1], sBhi + boff[j] + co);
                LDSM2(Blo[j][0], Blo[j][1], sBlo + boff[j] + co);
            }
#pragma unroll
            for (int i = 0; i < 4; i++)
#pragma unroll
                for (int j = 0; j < 4; j++) {
                    MMA16816(acc[i][j], Ahi[i], Bhi[j]);
                    MMA16816(acc[i][j], Ahi[i], Blo[j]);
                    MMA16816(acc[i][j], Alo[i], Bhi[j]);
                }
        }
        __syncthreads();
    }

    // epilogue: c0,c1 -> (row, col..col+1); c2,c3 -> (row+8, ...)
    const int erow = lane >> 2;
    const int ecol = (lane & 3) * 2;
#pragma unroll
    for (int i = 0; i < 4; i++) {
        const int m0 = bm + warp_m * 64 + i * 16 + erow;
#pragma unroll
        for (int j = 0; j < 4; j++) {
            const int n0 = bn + warp_n * 32 + j * 8 + ecol;
            float* p0 = g_hg + (size_t)m0 * N_TOT + n0;
            *reinterpret_cast<float2*>(p0) =
                make_float2(acc[i][j][0], acc[i][j][1]);
            float* p1 = p0 + (size_t)8 * N_TOT;
            *reinterpret_cast<float2*>(p1) =
                make_float2(acc[i][j][2], acc[i][j][3]);
        }
    }
}

// ---------------- scan ----------------
__device__ __forceinline__ void scan_terms(float hid, float gat, float& cc,
                                           float& zg) {
    float e = __expf(-gat);
    float z = __fdividef(1.f, 1.f + e);
    cc = e * z;
    float eh = __expf(-fabsf(hid));
    float sg = __fdividef(eh, 1.f + eh);
    float g = (hid >= 0.f) ? (hid + 0.5f) : sg;
    zg = z * g;
}

__global__ void scan_phase1() {
    const int gw = (blockIdx.x * blockDim.x + threadIdx.x) >> 5;
    const int lane = threadIdx.x & 31;
    const int chunk = gw & (NCHUNK - 1);
    const int dg = (gw >> 5) & 31;
    const int b = gw >> 10;
    const int d = dg * 32 + lane;

    const float* __restrict__ hg = g_hg;
    size_t base = ((size_t)(b * SEQL + chunk * CHUNK)) * N_TOT + d;
    float h = 0.f, p = 1.f;
#pragma unroll 8
    for (int l = 0; l < CHUNK; l++) {
        float hid = __ldg(hg + base + (size_t)l * N_TOT);
        float gat = __ldg(hg + base + (size_t)l * N_TOT + DIM);
        float cc, zg;
        scan_terms(hid, gat, cc, zg);
        h = cc * h + zg;
        p *= cc;
    }
    const int sidx = (b * NCHUNK + chunk) * DIM + d;
    g_sumH[sidx] = h;
    g_sumP[sidx] = p;
}

__global__ void scan_phase2() {
    const int idx = blockIdx.x * blockDim.x + threadIdx.x;
    const int b = idx >> 10;
    const int d = idx & (DIM - 1);
    float carry = 0.f;
#pragma unroll
    for (int ch = 0; ch < NCHUNK; ch++) {
        const int s = (b * NCHUNK + ch) * DIM + d;
        g_hstart[s] = carry;
        carry = g_sumP[s] * carry + g_sumH[s];
    }
}

__global__ void scan_phase3(float* __restrict__ out) {
    const int gw = (blockIdx.x * blockDim.x + threadIdx.x) >> 5;
    const int lane = threadIdx.x & 31;
    const int chunk = gw & (NCHUNK - 1);
    const int dg = (gw >> 5) & 31;
    const int b = gw >> 10;
    const int d = dg * 32 + lane;

    const float* __restrict__ hg = g_hg;
    size_t base = ((size_t)(b * SEQL + chunk * CHUNK)) * N_TOT + d;
    size_t obase = ((size_t)(b * SEQL + chunk * CHUNK)) * DIM + d;
    float h = g_hstart[(b * NCHUNK + chunk) * DIM + d];
#pragma unroll 8
    for (int l = 0; l < CHUNK; l++) {
        float hid = __ldg(hg + base + (size_t)l * N_TOT);
        float gat = __ldg(hg + base + (size_t)l * N_TOT + DIM);
        float cc, zg;
        scan_terms(hid, gat, cc, zg);
        h = cc * h + zg;
        out[obase + (size_t)l * DIM] = h;
    }
}

// ---------------- launch ----------------
extern "C" void kernel_launch(void* const* d_in, const int* in_sizes, int n_in,
                              void* d_out, int out_size) {
    const float* x = (const float*)d_in[0];   // [4,4096,1024]
    const float* W = (const float*)d_in[1];   // [2048,1024]
    float* out = (float*)d_out;               // [4,4096,1024]

    cudaFuncSetAttribute(gemm_mma_kernel,
                         cudaFuncAttributeMaxDynamicSharedMemorySize, SMEM_DYN);

    __half *xhi, *xlo, *whi, *wlo;
    cudaGetSymbolAddress((void**)&xhi, g_xhi);
    cudaGetSymbolAddress((void**)&xlo, g_xlo);
    cudaGetSymbolAddress((void**)&whi, g_whi);
    cudaGetSymbolAddress((void**)&wlo, g_wlo);
    split_kernel<<<(M_TOT * K_TOT / 4 + 255) / 256, 256>>>(x, xhi, xlo,
                                                           M_TOT * K_TOT / 4);
    split_kernel<<<(N_TOT * K_TOT / 4 + 255) / 256, 256>>>(W, whi, wlo,
                                                           N_TOT * K_TOT / 4);

    dim3 ggrid(N_TOT / 128, M_TOT / 128);   // (16, 128) — bn fastest for A reuse
    gemm_mma_kernel<<<ggrid, 256, SMEM_DYN>>>();

    scan_phase1<<<512, 256>>>();
    scan_phase2<<<16, 256>>>();
    scan_phase3<<<512, 256>>>(out);
}

// round 5
// speedup vs baseline: 4.7199x; 1.8860x over previous
#include <cuda_runtime.h>
#include <cuda_fp16.h>
#include <cstdint>

// Problem dims (fixed)
#define M_TOT 16384   // B*L
#define N_TOT 2048    // 2*D
#define K_TOT 1024    // D
#define BATCH 4
#define SEQL  4096
#define DIM   1024
#define NCHUNK 32
#define CHUNK  128

// ---------------- scratch ----------------
__device__ __align__(256) float  g_hg[(size_t)M_TOT * N_TOT];     // 134MB GEMM out
__device__ __align__(256) __half g_xh[(size_t)M_TOT * K_TOT];
__device__ __align__(256) __half g_wh[(size_t)N_TOT * K_TOT];
__device__ float g_sumP[BATCH * NCHUNK * DIM];
__device__ float g_sumH[BATCH * NCHUNK * DIM];
__device__ float g_hstart[BATCH * NCHUNK * DIM];

// ---------------- PTX helpers (base sm_100 legal only) ----------------
__device__ __forceinline__ uint32_t smem_u32(const void* p) {
    uint32_t a;
    asm("{ .reg .u64 t; cvta.to.shared.u64 t, %1; cvt.u32.u64 %0, t; }"
        : "=r"(a) : "l"(p));
    return a;
}
__device__ __forceinline__ void cp16(uint32_t dst, const void* src) {
    asm volatile("cp.async.cg.shared.global [%0], [%1], 16;" :: "r"(dst), "l"(src));
}
#define CP_COMMIT() asm volatile("cp.async.commit_group;" ::: "memory")
#define CP_WAIT0()  asm volatile("cp.async.wait_group 0;" ::: "memory")
#define CP_WAIT1()  asm volatile("cp.async.wait_group 1;" ::: "memory")
#define CP_WAIT2()  asm volatile("cp.async.wait_group 2;" ::: "memory")

#define LDSM4(r0, r1, r2, r3, a) \
    asm volatile("ldmatrix.sync.aligned.m8n8.x4.shared.b16 {%0,%1,%2,%3}, [%4];" \
                 : "=r"(r0), "=r"(r1), "=r"(r2), "=r"(r3) : "r"(a))
#define LDSM2(r0, r1, a) \
    asm volatile("ldmatrix.sync.aligned.m8n8.x2.shared.b16 {%0,%1}, [%2];" \
                 : "=r"(r0), "=r"(r1) : "r"(a))

#define MMA16816(c, a, b) \
    asm volatile( \
        "mma.sync.aligned.m16n8k16.row.col.f32.f16.f16.f32 " \
        "{%0,%1,%2,%3}, {%4,%5,%6,%7}, {%8,%9}, {%0,%1,%2,%3};" \
        : "+f"((c)[0]), "+f"((c)[1]), "+f"((c)[2]), "+f"((c)[3]) \
        : "r"((a)[0]), "r"((a)[1]), "r"((a)[2]), "r"((a)[3]), \
          "r"((b)[0]), "r"((b)[1]))

// ---------------- f32 -> f16 convert ----------------
__global__ void conv_kernel(const float* __restrict__ src,
                            __half* __restrict__ dst, int n4) {
    int i = blockIdx.x * blockDim.x + threadIdx.x;
    if (i >= n4) return;
    float4 v = reinterpret_cast<const float4*>(src)[i];
    reinterpret_cast<__half2*>(dst)[2 * i] =
        __halves2half2(__float2half_rn(v.x), __float2half_rn(v.y));
    reinterpret_cast<__half2*>(dst)[2 * i + 1] =
        __halves2half2(__float2half_rn(v.z), __float2half_rn(v.w));
}

// ---------------- mma.sync GEMM: 128M x 128N per CTA, BK=64, 4 stages ----
// Smem row = 64 halves = 128B; 16B chunks swizzled: chunk ^= (row & 7)
#define OFF_A 0
#define OFF_B 16384
#define STAGE_BYTES 32768
#define NSTAGES 4
#define SMEM_DYN (NSTAGES * STAGE_BYTES)
#define NT (K_TOT / 64)   // 16

__device__ __forceinline__ void load_stage(uint32_t sbase, int buf, int kc,
                                           int bm, int bn, int tid) {
    uint32_t s = sbase + (uint32_t)buf * STAGE_BYTES;
#pragma unroll
    for (int i = 0; i < 4; i++) {
        int ch = tid + i * 256;           // 0..1023
        int row = ch >> 3, c = ch & 7;
        uint32_t off = (uint32_t)(row * 128) + (uint32_t)((c ^ (row & 7)) << 4);
        cp16(s + OFF_A + off, g_xh + (size_t)(bm + row) * K_TOT + kc + c * 8);
        cp16(s + OFF_B + off, g_wh + (size_t)(bn + row) * K_TOT + kc + c * 8);
    }
    CP_COMMIT();
}

__global__ __launch_bounds__(256, 1) void gemm_mma_kernel() {
    extern __shared__ __align__(1024) char dyn_smem[];
    const int tid = threadIdx.x;
    const int wid = tid >> 5;
    const int lane = tid & 31;
    const int bm = blockIdx.y * 128;
    const int bn = blockIdx.x * 128;
    const int warp_m = wid & 1;     // 2 warps along M (64 rows each)
    const int warp_n = wid >> 1;    // 4 warps along N (32 cols each)

    uint32_t sbase = smem_u32(dyn_smem);

    // per-lane ldmatrix row precompute
    const int j4 = lane >> 3;            // matrix index for x4
    const int rin = lane & 7;
    const int a_moff = (j4 & 1) * 8 + rin;
    const int a_kj = j4 >> 1;            // 0/1: k-chunk within k16
    int aoff[4], asw[4];
#pragma unroll
    for (int i = 0; i < 4; i++) {
        int r = warp_m * 64 + i * 16 + a_moff;
        aoff[i] = r * 128;
        asw[i] = r & 7;
    }
    const int b_kj = (lane >> 3) & 1;    // matrix index for x2
    int boff[4], bsw[4];
#pragma unroll
    for (int j = 0; j < 4; j++) {
        int r = warp_n * 32 + j * 8 + rin;
        boff[j] = r * 128;
        bsw[j] = r & 7;
    }

    float acc[4][4][4];
#pragma unroll
    for (int i = 0; i < 4; i++)
#pragma unroll
        for (int j = 0; j < 4; j++)
#pragma unroll
            for (int q = 0; q < 4; q++) acc[i][j][q] = 0.f;

    // prologue: stages 0..2
    load_stage(sbase, 0, 0, bm, bn, tid);
    load_stage(sbase, 1, 64, bm, bn, tid);
    load_stage(sbase, 2, 128, bm, bn, tid);

#pragma unroll 1
    for (int t = 0; t < NT; t++) {
        // stage t ready: allow {t+1, t+2} pending
        if (t < NT - 2)      { CP_WAIT2(); }
        else if (t == NT - 2){ CP_WAIT1(); }
        else                 { CP_WAIT0(); }
        __syncthreads();

        // issue load t+3 into buffer (t+3)&3 == (t-1)&3; compute(t-1) done for
        // all warps (previous barrier), so overwrite is safe.
        if (t + 3 < NT) load_stage(sbase, (t + 3) & 3, (t + 3) * 64, bm, bn, tid);

        const uint32_t s = sbase + (uint32_t)(t & 3) * STAGE_BYTES;
        const uint32_t sA = s + OFF_A, sB = s + OFF_B;

#pragma unroll
        for (int ks = 0; ks < 4; ks++) {
            uint32_t Af[4][4], Bf[4][2];
#pragma unroll
            for (int i = 0; i < 4; i++) {
                uint32_t co = (uint32_t)(((ks * 2 + a_kj) ^ asw[i]) << 4);
                LDSM4(Af[i][0], Af[i][1], Af[i][2], Af[i][3], sA + aoff[i] + co);
            }
#pragma unroll
            for (int j = 0; j < 4; j++) {
                uint32_t co = (uint32_t)(((ks * 2 + b_kj) ^ bsw[j]) << 4);
                LDSM2(Bf[j][0], Bf[j][1], sB + boff[j] + co);
            }
#pragma unroll
            for (int i = 0; i < 4; i++)
#pragma unroll
                for (int j = 0; j < 4; j++) MMA16816(acc[i][j], Af[i], Bf[j]);
        }
    }

    // epilogue
    const int erow = lane >> 2;
    const int ecol = (lane & 3) * 2;
#pragma unroll
    for (int i = 0; i < 4; i++) {
        const int m0 = bm + warp_m * 64 + i * 16 + erow;
#pragma unroll
        for (int j = 0; j < 4; j++) {
            const int n0 = bn + warp_n * 32 + j * 8 + ecol;
            float* p0 = g_hg + (size_t)m0 * N_TOT + n0;
            *reinterpret_cast<float2*>(p0) =
                make_float2(acc[i][j][0], acc[i][j][1]);
            float* p1 = p0 + (size_t)8 * N_TOT;
            *reinterpret_cast<float2*>(p1) =
                make_float2(acc[i][j][2], acc[i][j][3]);
        }
    }
}

// ---------------- scan ----------------
__device__ __forceinline__ void scan_terms(float hid, float gat, float& cc,
                                           float& zg) {
    float e = __expf(-gat);
    float z = __fdividef(1.f, 1.f + e);
    cc = e * z;
    float eh = __expf(-fabsf(hid));
    float sg = __fdividef(eh, 1.f + eh);
    float g = (hid >= 0.f) ? (hid + 0.5f) : sg;
    zg = z * g;
}

__global__ void scan_phase1() {
    const int gw = (blockIdx.x * blockDim.x + threadIdx.x) >> 5;
    const int lane = threadIdx.x & 31;
    const int chunk = gw & (NCHUNK - 1);
    const int dg = (gw >> 5) & 31;
    const int b = gw >> 10;
    const int d = dg * 32 + lane;

    const float* __restrict__ hg = g_hg;
    size_t base = ((size_t)(b * SEQL + chunk * CHUNK)) * N_TOT + d;
    float h = 0.f, p = 1.f;
#pragma unroll 8
    for (int l = 0; l < CHUNK; l++) {
        float hid = __ldg(hg + base + (size_t)l * N_TOT);
        float gat = __ldg(hg + base + (size_t)l * N_TOT + DIM);
        float cc, zg;
        scan_terms(hid, gat, cc, zg);
        h = cc * h + zg;
        p *= cc;
    }
    const int sidx = (b * NCHUNK + chunk) * DIM + d;
    g_sumH[sidx] = h;
    g_sumP[sidx] = p;
}

__global__ void scan_phase2() {
    const int idx = blockIdx.x * blockDim.x + threadIdx.x;
    const int b = idx >> 10;
    const int d = idx & (DIM - 1);
    float carry = 0.f;
#pragma unroll
    for (int ch = 0; ch < NCHUNK; ch++) {
        const int s = (b * NCHUNK + ch) * DIM + d;
        g_hstart[s] = carry;
        carry = g_sumP[s] * carry + g_sumH[s];
    }
}

__global__ void scan_phase3(float* __restrict__ out) {
    const int gw = (blockIdx.x * blockDim.x + threadIdx.x) >> 5;
    const int lane = threadIdx.x & 31;
    const int chunk = gw & (NCHUNK - 1);
    const int dg = (gw >> 5) & 31;
    const int b = gw >> 10;
    const int d = dg * 32 + lane;

    const float* __restrict__ hg = g_hg;
    size_t base = ((size_t)(b * SEQL + chunk * CHUNK)) * N_TOT + d;
    size_t obase = ((size_t)(b * SEQL + chunk * CHUNK)) * DIM + d;
    float h = g_hstart[(b * NCHUNK + chunk) * DIM + d];
#pragma unroll 8
    for (int l = 0; l < CHUNK; l++) {
        float hid = __ldg(hg + base + (size_t)l * N_TOT);
        float gat = __ldg(hg + base + (size_t)l * N_TOT + DIM);
        float cc, zg;
        scan_terms(hid, gat, cc, zg);
        h = cc * h + zg;
        out[obase + (size_t)l * DIM] = h;
    }
}

// ---------------- launch ----------------
extern "C" void kernel_launch(void* const* d_in, const int* in_sizes, int n_in,
                              void* d_out, int out_size) {
    const float* x = (const float*)d_in[0];   // [4,4096,1024]
    const float* W = (const float*)d_in[1];   // [2048,1024]
    float* out = (float*)d_out;               // [4,4096,1024]

    cudaFuncSetAttribute(gemm_mma_kernel,
                         cudaFuncAttributeMaxDynamicSharedMemorySize, SMEM_DYN);

    __half *xh, *wh;
    cudaGetSymbolAddress((void**)&xh, g_xh);
    cudaGetSymbolAddress((void**)&wh, g_wh);
    conv_kernel<<<(M_TOT * K_TOT / 4 + 255) / 256, 256>>>(x, xh,
                                                          M_TOT * K_TOT / 4);
    conv_kernel<<<(N_TOT * K_TOT / 4 + 255) / 256, 256>>>(W, wh,
                                                          N_TOT * K_TOT / 4);

    dim3 ggrid(N_TOT / 128, M_TOT / 128);   // (16, 128)
    gemm_mma_kernel<<<ggrid, 256, SMEM_DYN>>>();

    scan_phase1<<<512, 256>>>();
    scan_phase2<<<16, 256>>>();
    scan_phase3<<<512, 256>>>(out);
}

// round 7
// speedup vs baseline: 5.1826x; 1.0980x over previous
#include <cuda_runtime.h>
#include <cuda_fp16.h>
#include <cstdint>

// Problem dims (fixed)
#define M_TOT 16384   // B*L
#define N_TOT 2048    // 2*D
#define K_TOT 1024    // D
#define BATCH 4
#define SEQL  4096
#define DIM   1024
#define NCHUNK 32
#define CHUNK  128

// ---------------- scratch ----------------
__device__ __align__(256) __half g_hgh[(size_t)M_TOT * N_TOT];   // 67MB GEMM out (fp16)
__device__ __align__(256) __half g_xh[(size_t)M_TOT * K_TOT];
__device__ __align__(256) __half g_wh[(size_t)N_TOT * K_TOT];
__device__ float g_sumP[BATCH * NCHUNK * DIM];
__device__ float g_sumH[BATCH * NCHUNK * DIM];
__device__ float g_hstart[BATCH * NCHUNK * DIM];

// ---------------- PTX helpers (base sm_100 legal only) ----------------
__device__ __forceinline__ uint32_t smem_u32(const void* p) {
    uint32_t a;
    asm("{ .reg .u64 t; cvta.to.shared.u64 t, %1; cvt.u32.u64 %0, t; }"
        : "=r"(a) : "l"(p));
    return a;
}
__device__ __forceinline__ void cp16(uint32_t dst, const void* src) {
    asm volatile("cp.async.cg.shared.global [%0], [%1], 16;" :: "r"(dst), "l"(src));
}
#define CP_COMMIT() asm volatile("cp.async.commit_group;" ::: "memory")
#define CP_WAIT0()  asm volatile("cp.async.wait_group 0;" ::: "memory")
#define CP_WAIT1()  asm volatile("cp.async.wait_group 1;" ::: "memory")
#define CP_WAIT2()  asm volatile("cp.async.wait_group 2;" ::: "memory")

#define LDSM4(r0, r1, r2, r3, a) \
    asm volatile("ldmatrix.sync.aligned.m8n8.x4.shared.b16 {%0,%1,%2,%3}, [%4];" \
                 : "=r"(r0), "=r"(r1), "=r"(r2), "=r"(r3) : "r"(a))

#define MMA16816(c, a, b) \
    asm volatile( \
        "mma.sync.aligned.m16n8k16.row.col.f32.f16.f16.f32 " \
        "{%0,%1,%2,%3}, {%4,%5,%6,%7}, {%8,%9}, {%0,%1,%2,%3};" \
        : "+f"((c)[0]), "+f"((c)[1]), "+f"((c)[2]), "+f"((c)[3]) \
        : "r"((a)[0]), "r"((a)[1]), "r"((a)[2]), "r"((a)[3]), \
          "r"((b)[0]), "r"((b)[1]))

// ---------------- f32 -> f16 convert ----------------
__global__ void conv_kernel(const float* __restrict__ src,
                            __half* __restrict__ dst, int n4) {
    int i = blockIdx.x * blockDim.x + threadIdx.x;
    if (i >= n4) return;
    float4 v = reinterpret_cast<const float4*>(src)[i];
    reinterpret_cast<__half2*>(dst)[2 * i] =
        __halves2half2(__float2half_rn(v.x), __float2half_rn(v.y));
    reinterpret_cast<__half2*>(dst)[2 * i + 1] =
        __halves2half2(__float2half_rn(v.z), __float2half_rn(v.w));
}

// ------------- mma.sync GEMM: 128M x 256N per CTA, BK=64, 4 stages -------
// Smem row = 64 halves = 128B; 16B chunks swizzled: chunk ^= (row & 7)
#define OFF_A 0
#define OFF_B 16384            // A: 128 rows, B: 256 rows
#define STAGE_BYTES 49152
#define NSTAGES 4
#define SMEM_DYN (NSTAGES * STAGE_BYTES)
#define NT (K_TOT / 64)   // 16

__device__ __forceinline__ void load_stage(uint32_t sbase, int buf, int kc,
                                           int bm, int bn, int tid) {
    uint32_t s = sbase + (uint32_t)buf * STAGE_BYTES;
#pragma unroll
    for (int i = 0; i < 4; i++) {      // A: 128 rows x 8 chunks = 1024
        int ch = tid + i * 256;
        int row = ch >> 3, c = ch & 7;
        uint32_t off = (uint32_t)(row * 128) + (uint32_t)((c ^ (row & 7)) << 4);
        cp16(s + OFF_A + off, g_xh + (size_t)(bm + row) * K_TOT + kc + c * 8);
    }
#pragma unroll
    for (int i = 0; i < 8; i++) {      // B: 256 rows x 8 chunks = 2048
        int ch = tid + i * 256;
        int row = ch >> 3, c = ch & 7;
        uint32_t off = (uint32_t)(row * 128) + (uint32_t)((c ^ (row & 7)) << 4);
        cp16(s + OFF_B + off, g_wh + (size_t)(bn + row) * K_TOT + kc + c * 8);
    }
    CP_COMMIT();
}

__global__ __launch_bounds__(256, 1) void gemm_mma_kernel() {
    extern __shared__ __align__(1024) char dyn_smem[];
    const int tid = threadIdx.x;
    const int wid = tid >> 5;
    const int lane = tid & 31;
    const int bm = blockIdx.y * 128;
    const int bn = blockIdx.x * 256;
    const int warp_m = wid & 1;     // 2 warps along M (64 rows each)
    const int warp_n = wid >> 1;    // 4 warps along N (64 cols each)

    uint32_t sbase = smem_u32(dyn_smem);

    const int j4 = lane >> 3;
    const int rin = lane & 7;
    // A x4: m0,m1 = rows 0-7/8-15 @k0; m2,m3 = same @k1
    const int a_moff = (j4 & 1) * 8 + rin;
    const int a_kj = j4 >> 1;
    int aoff[4], asw[4];
#pragma unroll
    for (int i = 0; i < 4; i++) {
        int r = warp_m * 64 + i * 16 + a_moff;
        aoff[i] = r * 128;
        asw[i] = r & 7;
    }
    // B x4: m0,m1 = n rows j*8.. @k0/k1; m2,m3 = (j+1)*8 @k0/k1
    const int b_noff = (j4 >> 1) * 8 + rin;
    const int b_kj = j4 & 1;
    int boff[4], bsw[4];
#pragma unroll
    for (int jj = 0; jj < 4; jj++) {
        int r = warp_n * 64 + jj * 16 + b_noff;
        boff[jj] = r * 128;
        bsw[jj] = r & 7;
    }

    float acc[4][8][4];
#pragma unroll
    for (int i = 0; i < 4; i++)
#pragma unroll
        for (int j = 0; j < 8; j++)
#pragma unroll
            for (int q = 0; q < 4; q++) acc[i][j][q] = 0.f;

    load_stage(sbase, 0, 0, bm, bn, tid);
    load_stage(sbase, 1, 64, bm, bn, tid);
    load_stage(sbase, 2, 128, bm, bn, tid);

#pragma unroll 1
    for (int t = 0; t < NT; t++) {
        if (t < NT - 2)      { CP_WAIT2(); }
        else if (t == NT - 2){ CP_WAIT1(); }
        else                 { CP_WAIT0(); }
        __syncthreads();

        if (t + 3 < NT) load_stage(sbase, (t + 3) & 3, (t + 3) * 64, bm, bn, tid);

        const uint32_t s = sbase + (uint32_t)(t & 3) * STAGE_BYTES;
        const uint32_t sA = s + OFF_A, sB = s + OFF_B;

#pragma unroll
        for (int ks = 0; ks < 4; ks++) {
            uint32_t Af[4][4], Bf[8][2];
#pragma unroll
            for (int i = 0; i < 4; i++) {
                uint32_t co = (uint32_t)(((ks * 2 + a_kj) ^ asw[i]) << 4);
                LDSM4(Af[i][0], Af[i][1], Af[i][2], Af[i][3], sA + aoff[i] + co);
            }
#pragma unroll
            for (int jj = 0; jj < 4; jj++) {
                uint32_t co = (uint32_t)(((ks * 2 + b_kj) ^ bsw[jj]) << 4);
                LDSM4(Bf[2 * jj][0], Bf[2 * jj][1], Bf[2 * jj + 1][0],
                      Bf[2 * jj + 1][1], sB + boff[jj] + co);
            }
#pragma unroll
            for (int i = 0; i < 4; i++)
#pragma unroll
                for (int j = 0; j < 8; j++) MMA16816(acc[i][j], Af[i], Bf[j]);
        }
    }

    // epilogue: fp16 store; acc quad -> (erow, ecol..ecol+1) and (erow+8, ..)
    const int erow = lane >> 2;
    const int ecol = (lane & 3) * 2;
    __half* hgh = g_hgh;
#pragma unroll
    for (int i = 0; i < 4; i++) {
        const int m0 = bm + warp_m * 64 + i * 16 + erow;
#pragma unroll
        for (int j = 0; j < 8; j++) {
            const int n0 = bn + warp_n * 64 + j * 8 + ecol;
            *reinterpret_cast<__half2*>(hgh + (size_t)m0 * N_TOT + n0) =
                __halves2half2(__float2half_rn(acc[i][j][0]),
                               __float2half_rn(acc[i][j][1]));
            *reinterpret_cast<__half2*>(hgh + (size_t)(m0 + 8) * N_TOT + n0) =
                __halves2half2(__float2half_rn(acc[i][j][2]),
                               __float2half_rn(acc[i][j][3]));
        }
    }
}

// ---------------- scan ----------------
__device__ __forceinline__ void scan_terms(float hid, float gat, float& cc,
                                           float& zg) {
    float e = __expf(-gat);
    float z = __fdividef(1.f, 1.f + e);
    cc = e * z;
    float eh = __expf(-fabsf(hid));
    float sg = __fdividef(eh, 1.f + eh);
    float g = (hid >= 0.f) ? (hid + 0.5f) : sg;
    zg = z * g;
}

__global__ void scan_phase1() {
    const int gw = (blockIdx.x * blockDim.x + threadIdx.x) >> 5;
    const int lane = threadIdx.x & 31;
    const int chunk = gw & (NCHUNK - 1);
    const int dg = (gw >> 5) & 31;
    const int b = gw >> 10;
    const int d = dg * 32 + lane;

    const __half* __restrict__ hg = g_hgh;
    size_t base = ((size_t)(b * SEQL + chunk * CHUNK)) * N_TOT + d;
    float h = 0.f, p = 1.f;
#pragma unroll 8
    for (int l = 0; l < CHUNK; l++) {
        float hid = __half2float(__ldg(hg + base + (size_t)l * N_TOT));
        float gat = __half2float(__ldg(hg + base + (size_t)l * N_TOT + DIM));
        float cc, zg;
        scan_terms(hid, gat, cc, zg);
        h = cc * h + zg;
        p *= cc;
    }
    const int sidx = (b * NCHUNK + chunk) * DIM + d;
    g_sumH[sidx] = h;
    g_sumP[sidx] = p;
}

__global__ void scan_phase2() {
    const int idx = blockIdx.x * blockDim.x + threadIdx.x;
    const int b = idx >> 10;
    const int d = idx & (DIM - 1);
    float carry = 0.f;
#pragma unroll
    for (int ch = 0; ch < NCHUNK; ch++) {
        const int s = (b * NCHUNK + ch) * DIM + d;
        g_hstart[s] = carry;
        carry = g_sumP[s] * carry + g_sumH[s];
    }
}

__global__ void scan_phase3(float* __restrict__ out) {
    const int gw = (blockIdx.x * blockDim.x + threadIdx.x) >> 5;
    const int lane = threadIdx.x & 31;
    const int chunk = gw & (NCHUNK - 1);
    const int dg = (gw >> 5) & 31;
    const int b = gw >> 10;
    const int d = dg * 32 + lane;

    const __half* __restrict__ hg = g_hgh;
    size_t base = ((size_t)(b * SEQL + chunk * CHUNK)) * N_TOT + d;
    size_t obase = ((size_t)(b * SEQL + chunk * CHUNK)) * DIM + d;
    float h = g_hstart[(b * NCHUNK + chunk) * DIM + d];
#pragma unroll 8
    for (int l = 0; l < CHUNK; l++) {
        float hid = __half2float(__ldg(hg + base + (size_t)l * N_TOT));
        float gat = __half2float(__ldg(hg + base + (size_t)l * N_TOT + DIM));
        float cc, zg;
        scan_terms(hid, gat, cc, zg);
        h = cc * h + zg;
        out[obase + (size_t)l * DIM] = h;
    }
}

// ---------------- launch ----------------
extern "C" void kernel_launch(void* const* d_in, const int* in_sizes, int n_in,
                              void* d_out, int out_size) {
    const float* x = (const float*)d_in[0];   // [4,4096,1024]
    const float* W = (const float*)d_in[1];   // [2048,1024]
    float* out = (float*)d_out;               // [4,4096,1024]

    cudaFuncSetAttribute(gemm_mma_kernel,
                         cudaFuncAttributeMaxDynamicSharedMemorySize, SMEM_DYN);

    __half *xh, *wh;
    cudaGetSymbolAddress((void**)&xh, g_xh);
    cudaGetSymbolAddress((void**)&wh, g_wh);
    conv_kernel<<<(M_TOT * K_TOT / 4 + 255) / 256, 256>>>(x, xh,
                                                          M_TOT * K_TOT / 4);
    conv_kernel<<<(N_TOT * K_TOT / 4 + 255) / 256, 256>>>(W, wh,
                                                          N_TOT * K_TOT / 4);

    dim3 ggrid(N_TOT / 256, M_TOT / 128);   // (8, 128)
    gemm_mma_kernel<<<ggrid, 256, SMEM_DYN>>>();

    scan_phase1<<<512, 256>>>();
    scan_phase2<<<16, 256>>>();
    scan_phase3<<<512, 256>>>(out);
}